// round 16
// baseline (speedup 1.0000x reference)
#include <cuda_runtime.h>
#include <cuda_fp16.h>
#include <cstdint>

// Problem constants
#define GRID_HW 512
#define BATCH 4
#define NFEAT 16
#define NPOINTS (BATCH * GRID_HW * GRID_HW)   // 1,048,576
#define OUT_PLANE (GRID_HW * GRID_HW)         // 262,144

// Transposed fp16 texture scratch: layout (H, W, F) per mip, F innermost.
// Sizes (halves): 1024^2*16 + 512^2*16 + 256^2*16 + 128^2*16 = 22,282,240
#define SCRATCH_HALVES 22282240
__device__ __align__(16) __half g_tex[SCRATCH_HALVES];

// ---------------------------------------------------------------------------
// Kernel 1: transpose ALL mips (F,H,W) fp32 -> (H,W,F) fp16, one launch.
// Block ranges: [0,4096) mip1, [4096,5120) mip2, [5120,5376) mip3,
// [5376,5440) mip4. One thread per texel. DRAM-bound (~134MB); left as-is.
// ---------------------------------------------------------------------------
__global__ __launch_bounds__(256) void transpose_all(
    const float* __restrict__ t1, const float* __restrict__ t2,
    const float* __restrict__ t3, const float* __restrict__ t4) {
    int blk = blockIdx.x;
    const float* src;
    int HW, offH, i;
    if (blk < 4096)      { src = t1; HW = 1 << 20; offH = 0;        i = blk * 256; }
    else if (blk < 5120) { src = t2; HW = 1 << 18; offH = 16777216; i = (blk - 4096) * 256; }
    else if (blk < 5376) { src = t3; HW = 1 << 16; offH = 20971520; i = (blk - 5120) * 256; }
    else                 { src = t4; HW = 1 << 14; offH = 22020096; i = (blk - 5376) * 256; }
    i += threadIdx.x;

    __half2 h[8];
#pragma unroll
    for (int f = 0; f < 8; f++) {
        float a = src[(size_t)(2 * f) * HW + i];
        float b = src[(size_t)(2 * f + 1) * HW + i];
        h[f] = __floats2half2_rn(a, b);
    }
    uint4* dst = reinterpret_cast<uint4*>(g_tex + offH + (size_t)i * NFEAT);
    dst[0] = *reinterpret_cast<const uint4*>(&h[0]);
    dst[1] = *reinterpret_cast<const uint4*>(&h[4]);
}

// ---------------------------------------------------------------------------
// Kernel 2: bilinear grid-sample (border, align_corners=False) over 4 mips.
// FOUR lanes per point: sub = lane&3, featHalf = sub&1, tap = sub>>1.
// Each lane: 2x LDG.128 per mip (rows y0,y1). 4-lane groups cover 64B
// contiguous spans. Cross-tap sum via shfl_xor(2).
// __ldcs on grid (read-once) and __stcs on out (write-once, evict-first)
// so the 44.6MB fp16 texture set stays L2-resident.
// ---------------------------------------------------------------------------
__global__ __launch_bounds__(256, 8) void sample_kernel(
    const float2* __restrict__ grid, float* __restrict__ out) {
    int t = blockIdx.x * 256 + threadIdx.x;      // 4M threads
    int p        = t >> 2;                        // point id
    int sub      = t & 3;
    int featHalf = sub & 1;
    int tap      = sub >> 1;

    float2 g = __ldcs(&grid[p]);                  // streaming read-once

    const int Ws[4]    = {1024, 512, 256, 128};
    const int offU4[4] = {0, 2097152, 2621440, 2752512};
    const uint4* gt = reinterpret_cast<const uint4*>(g_tex);

    // wxt = tap ? wx : (1-wx)  ==  base + sgn*wx  (one FMA, no select chain)
    const float wbase = tap ? 0.0f : 1.0f;
    const float wsgn  = tap ? 1.0f : -1.0f;

    uint4 ld[8];
    float w0[4], w1[4];

#pragma unroll
    for (int m = 0; m < 4; m++) {
        const int   W  = Ws[m];
        const float fW = (float)W;
        float ix = fminf(fmaxf(((g.x + 1.0f) * fW - 1.0f) * 0.5f, 0.0f), fW - 1.0f);
        float iy = fminf(fmaxf(((g.y + 1.0f) * fW - 1.0f) * 0.5f, 0.0f), fW - 1.0f);
        float x0f = floorf(ix), y0f = floorf(iy);
        float wx = ix - x0f, wy = iy - y0f;
        int x0 = (int)x0f, y0 = (int)y0f;
        int y1 = min(y0 + 1, W - 1);
        int xt = min(x0 + tap, W - 1);          // this lane's x tap
        float wxt = fmaf(wsgn, wx, wbase);
        w0[m] = wxt * (1.0f - wy);
        w1[m] = wxt * wy;

        const uint4* bp = gt + offU4[m];
        ld[2 * m]     = bp[(size_t)(y0 * W + xt) * 2 + featHalf];
        ld[2 * m + 1] = bp[(size_t)(y1 * W + xt) * 2 + featHalf];
    }

    // Accumulate 8 features (4 half2) in fp32
    float2 acc[4];
#pragma unroll
    for (int j = 0; j < 4; j++) acc[j] = make_float2(0.f, 0.f);
#pragma unroll
    for (int m = 0; m < 4; m++) {
        const __half2* h0 = reinterpret_cast<const __half2*>(&ld[2 * m]);
        const __half2* h1 = reinterpret_cast<const __half2*>(&ld[2 * m + 1]);
#pragma unroll
        for (int j = 0; j < 4; j++) {
            float2 v0 = __half22float2(h0[j]);
            float2 v1 = __half22float2(h1[j]);
            acc[j].x = fmaf(w0[m], v0.x, fmaf(w1[m], v1.x, acc[j].x));
            acc[j].y = fmaf(w0[m], v0.y, fmaf(w1[m], v1.y, acc[j].y));
        }
    }

    // Sum the two x-taps: partner lane = lane ^ 2 (same point, same featHalf)
#pragma unroll
    for (int j = 0; j < 4; j++) {
        acc[j].x += __shfl_xor_sync(0xFFFFFFFFu, acc[j].x, 2);
        acc[j].y += __shfl_xor_sync(0xFFFFFFFFu, acc[j].y, 2);
    }

    // Each lane writes 4 features: f0 = featHalf*8 + tap*4 (all lanes active).
    // __stcs: evict-first — out is write-once, keep textures in L2.
    int wo = p & (GRID_HW - 1);
    int ho = (p >> 9) & (GRID_HW - 1);
    int b  = p >> 18;
    int f0 = featHalf * 8 + tap * 4;
    int jb = tap * 2;   // acc[jb], acc[jb+1] hold feats f0..f0+3 of this half
    float* o = out + ((size_t)b * NFEAT + f0) * OUT_PLANE
                   + (size_t)ho * GRID_HW + wo;
    __stcs(o,                          acc[jb].x);
    __stcs(o + OUT_PLANE,              acc[jb].y);
    __stcs(o + (size_t)2 * OUT_PLANE,  acc[jb + 1].x);
    __stcs(o + (size_t)3 * OUT_PLANE,  acc[jb + 1].y);
}

// ---------------------------------------------------------------------------
extern "C" void kernel_launch(void* const* d_in, const int* in_sizes, int n_in,
                              void* d_out, int out_size) {
    const float* x    = (const float*)d_in[0];  // (B, 512, 512, 2)
    const float* tex1 = (const float*)d_in[1];  // (16, 1024, 1024)
    const float* tex2 = (const float*)d_in[2];  // (16, 512, 512)
    const float* tex3 = (const float*)d_in[3];  // (16, 256, 256)
    const float* tex4 = (const float*)d_in[4];  // (16, 128, 128)
    float* out = (float*)d_out;

    transpose_all<<<5440, 256>>>(tex1, tex2, tex3, tex4);

    // 4 lanes per point -> 4M threads
    sample_kernel<<<(NPOINTS * 4) / 256, 256>>>(
        reinterpret_cast<const float2*>(x), out);
}

// round 17
// speedup vs baseline: 1.0004x; 1.0004x over previous
#include <cuda_runtime.h>
#include <cuda_fp16.h>
#include <cstdint>

// Problem constants
#define GRID_HW 512
#define BATCH 4
#define NFEAT 16
#define NPOINTS (BATCH * GRID_HW * GRID_HW)   // 1,048,576
#define OUT_PLANE (GRID_HW * GRID_HW)         // 262,144

// Transposed fp16 texture scratch: layout (H, W, F) per mip, F innermost.
// Sizes (halves): 1024^2*16 + 512^2*16 + 256^2*16 + 128^2*16 = 22,282,240
#define SCRATCH_HALVES 22282240
__device__ __align__(16) __half g_tex[SCRATCH_HALVES];

// ---------------------------------------------------------------------------
// Kernel 1: transpose ALL mips (F,H,W) fp32 -> (H,W,F) fp16, one launch.
// DRAM-bound (~112MB); left as-is.
// ---------------------------------------------------------------------------
__global__ __launch_bounds__(256) void transpose_all(
    const float* __restrict__ t1, const float* __restrict__ t2,
    const float* __restrict__ t3, const float* __restrict__ t4) {
    int blk = blockIdx.x;
    const float* src;
    int HW, offH, i;
    if (blk < 4096)      { src = t1; HW = 1 << 20; offH = 0;        i = blk * 256; }
    else if (blk < 5120) { src = t2; HW = 1 << 18; offH = 16777216; i = (blk - 4096) * 256; }
    else if (blk < 5376) { src = t3; HW = 1 << 16; offH = 20971520; i = (blk - 5120) * 256; }
    else                 { src = t4; HW = 1 << 14; offH = 22020096; i = (blk - 5376) * 256; }
    i += threadIdx.x;

    __half2 h[8];
#pragma unroll
    for (int f = 0; f < 8; f++) {
        float a = src[(size_t)(2 * f) * HW + i];
        float b = src[(size_t)(2 * f + 1) * HW + i];
        h[f] = __floats2half2_rn(a, b);
    }
    uint4* dst = reinterpret_cast<uint4*>(g_tex + offH + (size_t)i * NFEAT);
    dst[0] = *reinterpret_cast<const uint4*>(&h[0]);
    dst[1] = *reinterpret_cast<const uint4*>(&h[4]);
}

// ---------------------------------------------------------------------------
// Kernel 2: bilinear grid-sample (border, align_corners=False) over 4 mips.
// FOUR lanes per point: sub = lane&3, featHalf = sub&1, tap = sub>>1.
// Each lane: 2x LDG.128 per mip (rows y0,y1). Cross-tap sum via shfl_xor(2).
// NEW: smem store staging — block's 64 points x 16 feats staged in shared,
// then written as plane-contiguous float4 STGs (store wf 2.0 -> ~0.5/pt).
// ---------------------------------------------------------------------------
__global__ __launch_bounds__(256, 8) void sample_kernel(
    const float2* __restrict__ grid, float* __restrict__ out) {
    __shared__ float sOut[NFEAT][68];             // 68-float rows: pad vs banks

    int t = blockIdx.x * 256 + threadIdx.x;       // 4M threads
    int p        = t >> 2;                        // point id
    int sub      = t & 3;
    int featHalf = sub & 1;
    int tap      = sub >> 1;

    float2 g = __ldcs(&grid[p]);                  // streaming read-once

    const int Ws[4]    = {1024, 512, 256, 128};
    const int offU4[4] = {0, 2097152, 2621440, 2752512};
    const uint4* gt = reinterpret_cast<const uint4*>(g_tex);

    // wxt = tap ? wx : (1-wx)  ==  base + sgn*wx
    const float wbase = tap ? 0.0f : 1.0f;
    const float wsgn  = tap ? 1.0f : -1.0f;

    uint4 ld[8];
    float w0[4], w1[4];

#pragma unroll
    for (int m = 0; m < 4; m++) {
        const int   W  = Ws[m];
        const float fW = (float)W;
        float ix = fminf(fmaxf(((g.x + 1.0f) * fW - 1.0f) * 0.5f, 0.0f), fW - 1.0f);
        float iy = fminf(fmaxf(((g.y + 1.0f) * fW - 1.0f) * 0.5f, 0.0f), fW - 1.0f);
        float x0f = floorf(ix), y0f = floorf(iy);
        float wx = ix - x0f, wy = iy - y0f;
        int x0 = (int)x0f, y0 = (int)y0f;
        int y1 = min(y0 + 1, W - 1);
        int xt = min(x0 + tap, W - 1);          // this lane's x tap
        float wxt = fmaf(wsgn, wx, wbase);
        w0[m] = wxt * (1.0f - wy);
        w1[m] = wxt * wy;

        const uint4* bp = gt + offU4[m];
        ld[2 * m]     = bp[(size_t)(y0 * W + xt) * 2 + featHalf];
        ld[2 * m + 1] = bp[(size_t)(y1 * W + xt) * 2 + featHalf];
    }

    // Accumulate 8 features (4 half2) in fp32
    float2 acc[4];
#pragma unroll
    for (int j = 0; j < 4; j++) acc[j] = make_float2(0.f, 0.f);
#pragma unroll
    for (int m = 0; m < 4; m++) {
        const __half2* h0 = reinterpret_cast<const __half2*>(&ld[2 * m]);
        const __half2* h1 = reinterpret_cast<const __half2*>(&ld[2 * m + 1]);
#pragma unroll
        for (int j = 0; j < 4; j++) {
            float2 v0 = __half22float2(h0[j]);
            float2 v1 = __half22float2(h1[j]);
            acc[j].x = fmaf(w0[m], v0.x, fmaf(w1[m], v1.x, acc[j].x));
            acc[j].y = fmaf(w0[m], v0.y, fmaf(w1[m], v1.y, acc[j].y));
        }
    }

    // Sum the two x-taps: partner lane = lane ^ 2 (same point, same featHalf)
#pragma unroll
    for (int j = 0; j < 4; j++) {
        acc[j].x += __shfl_xor_sync(0xFFFFFFFFu, acc[j].x, 2);
        acc[j].y += __shfl_xor_sync(0xFFFFFFFFu, acc[j].y, 2);
    }

    // Stage: this lane owns feats f0..f0+3 of local point pl.
    int pl = threadIdx.x >> 2;                    // 0..63
    int f0 = featHalf * 8 + tap * 4;
    int jb = tap * 2;
    sOut[f0 + 0][pl] = acc[jb].x;
    sOut[f0 + 1][pl] = acc[jb].y;
    sOut[f0 + 2][pl] = acc[jb + 1].x;
    sOut[f0 + 3][pl] = acc[jb + 1].y;
    __syncthreads();

    // Store phase: thread -> (plane f, 4-point chunk i). Per plane the block
    // writes 64 consecutive wo positions (256B contiguous) via float4 STGs.
    int f = threadIdx.x >> 4;                     // 0..15
    int i = threadIdx.x & 15;                     // 0..15
    float4 v = *reinterpret_cast<const float4*>(&sOut[f][4 * i]);

    int P0  = blockIdx.x * 64;                    // block's first point
    int b   = P0 >> 18;
    int ho  = (P0 >> 9) & (GRID_HW - 1);
    int wo0 = P0 & (GRID_HW - 1);                 // multiple of 64
    float4* o = reinterpret_cast<float4*>(
        out + ((size_t)b * NFEAT + f) * OUT_PLANE
            + (size_t)ho * GRID_HW + wo0 + 4 * i);
    __stcs(o, v);
}

// ---------------------------------------------------------------------------
extern "C" void kernel_launch(void* const* d_in, const int* in_sizes, int n_in,
                              void* d_out, int out_size) {
    const float* x    = (const float*)d_in[0];  // (B, 512, 512, 2)
    const float* tex1 = (const float*)d_in[1];  // (16, 1024, 1024)
    const float* tex2 = (const float*)d_in[2];  // (16, 512, 512)
    const float* tex3 = (const float*)d_in[3];  // (16, 256, 256)
    const float* tex4 = (const float*)d_in[4];  // (16, 128, 128)
    float* out = (float*)d_out;

    transpose_all<<<5440, 256>>>(tex1, tex2, tex3, tex4);

    // 4 lanes per point -> 4M threads
    sample_kernel<<<(NPOINTS * 4) / 256, 256>>>(
        reinterpret_cast<const float2*>(x), out);
}